// round 12
// baseline (speedup 1.0000x reference)
#include <cuda_runtime.h>
#include <cuda_fp16.h>
#include <cstdint>

// ---------------- problem constants ----------------
#define BDIM   4096
#define IDIM   256
#define ODIM   256
#define KBASIS (IDIM * 64)           // 16384
#define KTOT   (KBASIS + 2 * IDIM)   // 16896
#define NTOT   (2 * ODIM)            // 512

// GEMM tiling
#define MTILE  128
#define NTILE  128
#define KC     128                   // halves per stage-row = 256 B
#define STAGES 3
#define NST    (KTOT / KC)           // 132

// ---------------- scratch (device globals; no allocs allowed) ----------------
__device__ __align__(16) __half g_A[(size_t)BDIM * KTOT];    // 138 MB: [b][k] fp16
__device__ __align__(16) __half g_Wt[(size_t)NTOT * KTOT];   // 17.3 MB: [n][k] fp16 (K-major)
__device__ float g_bias[NTOT];

// ---------------- helpers ----------------
__device__ __forceinline__ uint32_t smem_u32(const void* p) {
    uint32_t a;
    asm("{ .reg .u64 t; cvta.to.shared.u64 t, %1; cvt.u32.u64 %0, t; }" : "=r"(a) : "l"(p));
    return a;
}

__device__ __forceinline__ void cp16s(uint32_t sm, const void* gm) {
    asm volatile("cp.async.cg.shared.global [%0], [%1], 16;\n" :: "r"(sm), "l"(gm) : "memory");
}

__device__ __forceinline__ void ldsm4(uint32_t* r, uint32_t addr) {
    asm volatile("ldmatrix.sync.aligned.m8n8.x4.shared.b16 {%0,%1,%2,%3}, [%4];"
                 : "=r"(r[0]), "=r"(r[1]), "=r"(r[2]), "=r"(r[3]) : "r"(addr));
}

__device__ __forceinline__ void mma_f16(float* d, const uint32_t* a, uint32_t b0, uint32_t b1) {
    asm volatile(
        "mma.sync.aligned.m16n8k16.row.col.f32.f16.f16.f32 "
        "{%0,%1,%2,%3},{%4,%5,%6,%7},{%8,%9},{%0,%1,%2,%3};"
        : "+f"(d[0]), "+f"(d[1]), "+f"(d[2]), "+f"(d[3])
        : "r"(a[0]), "r"(a[1]), "r"(a[2]), "r"(a[3]), "r"(b0), "r"(b1));
}

// ---------------- fused prep: basis+silu (x-part) and weights+bias (w-part) ----------------
// grid.x = 16384 (x-part: 4096 b x 4 i-groups) + 9728 (w-part) = 26112 blocks, 256 threads.
#define XBLOCKS 16384
#define WT_BLOCKS 8192
#define WS_BLOCKS 1024

__global__ void prep_all(const float* __restrict__ xre, const float* __restrict__ xim,
                         const float* __restrict__ rw, const float* __restrict__ cw,
                         const float* __restrict__ swre, const float* __restrict__ swim,
                         const float* __restrict__ bre, const float* __restrict__ bim) {
    const int bid = blockIdx.x;
    const int t   = threadIdx.x;

    if (bid < XBLOCKS) {
        // ---- x-part: one (b, i-group of 64) per block ----
        __shared__ float eu[64][8];
        __shared__ __half2 ev[64][4];
        const int b  = bid >> 2;
        const int i0 = (bid & 3) * 64;

        // 256 tasks: il(64) x comp(2) x half(2); each thread computes 4 exps
        {
            const int il   = t >> 2;
            const int comp = (t >> 1) & 1;
            const int hf   = t & 1;
            const float x  = (comp ? xim : xre)[b * IDIM + i0 + il];
            if (comp == 0) {
#pragma unroll
                for (int j = 0; j < 4; j++) {
                    int u = hf * 4 + j;
                    float lu = -2.0f + (float)u * (4.0f / 7.0f);
                    float d  = x - lu;
                    eu[il][u] = __expf(-d * d);
                }
            } else {
#pragma unroll
                for (int j = 0; j < 2; j++) {
                    int vp = hf * 2 + j;       // half2 pair index
                    float l0 = -2.0f + (float)(2 * vp) * (4.0f / 7.0f);
                    float l1 = l0 + (4.0f / 7.0f);
                    float d0 = x - l0, d1 = x - l1;
                    ev[il][vp] = __floats2half2_rn(__expf(-d0 * d0), __expf(-d1 * d1));
                }
            }
        }

        if ((bid & 3) == 0) {
            float xr = xre[b * IDIM + t];
            float xi = xim[b * IDIM + t];
            g_A[(size_t)b * KTOT + KBASIS + t]       = __float2half_rn(xr / (1.0f + __expf(-xr)));
            g_A[(size_t)b * KTOT + KBASIS + 256 + t] = __float2half_rn(xi / (1.0f + __expf(-xi)));
        }
        __syncthreads();

        const size_t base = (size_t)b * KTOT + (size_t)i0 * 64;
#pragma unroll
        for (int h8 = 0; h8 < 2; h8++) {
            int e0 = t * 16 + h8 * 8;
            int il = e0 >> 6;
            int u  = (e0 >> 3) & 7;
            __half2 b2 = __float2half2_rn(eu[il][u]);
            __half2 p0 = __hmul2(b2, ev[il][0]);
            __half2 p1 = __hmul2(b2, ev[il][1]);
            __half2 p2 = __hmul2(b2, ev[il][2]);
            __half2 p3 = __hmul2(b2, ev[il][3]);
            uint4 pack;
            pack.x = *(uint32_t*)&p0; pack.y = *(uint32_t*)&p1;
            pack.z = *(uint32_t*)&p2; pack.w = *(uint32_t*)&p3;
            *(uint4*)&g_A[base + e0] = pack;
        }
    } else if (bid < XBLOCKS + WT_BLOCKS) {
        // ---- weights -> Wt[n][k] K-major fp16 ----
        int idx = (bid - XBLOCKS) * 256 + t;  // 512*256*16
        int f4 = idx & 15;
        int i  = (idx >> 4) & 255;
        int n  = idx >> 12;               // 0..511
        int o = n >> 1, c = n & 1;
        const float* src = c ? cw : rw;
        float4 w = *(const float4*)&src[((size_t)(i * ODIM + o)) * 64 + f4 * 4];
        size_t dst = (size_t)n * KTOT + i * 64 + f4 * 4;
        *(__half2*)&g_Wt[dst]     = __floats2half2_rn(w.x, w.y);
        *(__half2*)&g_Wt[dst + 2] = __floats2half2_rn(w.z, w.w);
    } else if (bid < XBLOCKS + WT_BLOCKS + WS_BLOCKS) {
        // ---- silu weight cols of Wt ----
        int idx = (bid - XBLOCKS - WT_BLOCKS) * 256 + t; // 512*512
        int j = idx & 511;
        int n = idx >> 9;
        int o = n >> 1, c = n & 1;
        float v;
        if (j < 256) { int i = j;       v = c ? swim[i * ODIM + o] : swre[i * ODIM + o]; }
        else         { int i = j - 256; v = c ? swre[i * ODIM + o] : -swim[i * ODIM + o]; }
        g_Wt[(size_t)n * KTOT + KBASIS + j] = __float2half_rn(v);
    } else {
        // ---- bias column sums ----
        int n = bid - (XBLOCKS + WT_BLOCKS + WS_BLOCKS);
        int o = n >> 1;
        const float* src = (n & 1) ? bim : bre;
        float v = src[t * ODIM + o];
#pragma unroll
        for (int off = 16; off; off >>= 1) v += __shfl_down_sync(0xffffffffu, v, off);
        __shared__ float red[8];
        if ((t & 31) == 0) red[t >> 5] = v;
        __syncthreads();
        if (t == 0) {
            float s = 0.0f;
#pragma unroll
            for (int w = 0; w < 8; w++) s += red[w];
            g_bias[n] = s;
        }
    }
}

// ---------------- GEMM: fp16 mma, 128x128 tile, warps = 2x2 spatial x 2 k-slices ----------------
#define STAGE_A     (MTILE * 256)           // 32768 B
#define STAGE_BYTES (2 * STAGE_A)           // 65536 B
#define SMEM_BYTES  (STAGES * STAGE_BYTES)  // 196608 B

__device__ __forceinline__ uint32_t swz(int r, int c) {
    return (uint32_t)(r * 256 + (c >> 3) * 128 + (((c & 7) ^ (r & 7)) * 16));
}

__device__ __forceinline__ void load_stage(uint32_t sbase, int m0, int n0, int kt, int buf, int tid) {
    uint32_t sa  = sbase + buf * STAGE_BYTES;
    uint32_t sbb = sa + STAGE_A;
    const __half* Ap = g_A  + (size_t)m0 * KTOT + (size_t)kt * KC;
    const __half* Bp = g_Wt + (size_t)n0 * KTOT + (size_t)kt * KC;
#pragma unroll
    for (int j = 0; j < 8; j++) {
        int id = tid + 256 * j;                // 2048 chunks of 16B
        int r = id >> 4, c = id & 15;
        cp16s(sa + swz(r, c), Ap + (size_t)r * KTOT + c * 8);
    }
#pragma unroll
    for (int j = 0; j < 8; j++) {
        int id = tid + 256 * j;
        int r = id >> 4, c = id & 15;
        cp16s(sbb + swz(r, c), Bp + (size_t)r * KTOT + c * 8);
    }
    asm volatile("cp.async.commit_group;" ::: "memory");
}

__global__ __launch_bounds__(256, 1) void gemm_kernel(float* __restrict__ out) {
    extern __shared__ char smem_raw[];
    const uint32_t sb = smem_u32(smem_raw);

    const int tid  = threadIdx.x;
    const int lane = tid & 31;
    const int warp = tid >> 5;
    const int kg   = warp >> 2;        // k-slice: 0 -> chunks 0..7, 1 -> chunks 8..15
    const int wm   = (warp >> 1) & 1;  // 2 spatial rows of 64
    const int wn   = warp & 1;         // 2 spatial cols of 64
    const int lr   = lane & 15;
    const int lh   = lane >> 4;
    // n fastest in blockIdx.x so the 4 CTAs sharing an A-slice are adjacent
    const int n0   = blockIdx.x * NTILE;
    const int m0   = blockIdx.y * MTILE;

    float acc[4][8][4];
#pragma unroll
    for (int a = 0; a < 4; a++)
#pragma unroll
        for (int b = 0; b < 8; b++)
#pragma unroll
            for (int c = 0; c < 4; c++) acc[a][b][c] = 0.0f;

    // prologue: stages 0,1
    load_stage(sb, m0, n0, 0, 0, tid);
    load_stage(sb, m0, n0, 1, 1, tid);

    uint32_t afr[2][4][4];
    uint32_t bfr[2][4][4];

    for (int kt = 0; kt < NST; kt++) {
        if (kt < NST - 1) asm volatile("cp.async.wait_group 1;" ::: "memory");
        else              asm volatile("cp.async.wait_group 0;" ::: "memory");
        __syncthreads();

        if (kt + 2 < NST) load_stage(sb, m0, n0, kt + 2, (kt + 2) % STAGES, tid);

        const int buf = kt % STAGES;
        const uint32_t sa  = sb + buf * STAGE_BYTES;
        const uint32_t sbb = sa + STAGE_A;

        // fragment ks_local = 0
        {
            const int c = kg * 8 + lh;
            const uint32_t cc = (uint32_t)((c >> 3) * 128 + (((c & 7) ^ (lr & 7)) * 16));
#pragma unroll
            for (int mt = 0; mt < 4; mt++)
                ldsm4(afr[0][mt], sa + (uint32_t)(wm * 64 + mt * 16 + lr) * 256 + cc);
#pragma unroll
            for (int nb = 0; nb < 4; nb++)
                ldsm4(bfr[0][nb], sbb + (uint32_t)(wn * 64 + nb * 16 + lr) * 256 + cc);
        }

#pragma unroll
        for (int ks = 0; ks < 4; ks++) {
            const int cur = ks & 1;
            if (ks < 3) {
                const int nxt = cur ^ 1;
                const int c = kg * 8 + (ks + 1) * 2 + lh;
                const uint32_t cc = (uint32_t)((c >> 3) * 128 + (((c & 7) ^ (lr & 7)) * 16));
#pragma unroll
                for (int mt = 0; mt < 4; mt++)
                    ldsm4(afr[nxt][mt], sa + (uint32_t)(wm * 64 + mt * 16 + lr) * 256 + cc);
#pragma unroll
                for (int nb = 0; nb < 4; nb++)
                    ldsm4(bfr[nxt][nb], sbb + (uint32_t)(wn * 64 + nb * 16 + lr) * 256 + cc);
            }
#pragma unroll
            for (int mt = 0; mt < 4; mt++)
#pragma unroll
                for (int nt = 0; nt < 8; nt++) {
                    int nb = nt >> 1, hi = nt & 1;
                    mma_f16(acc[mt][nt], afr[cur][mt], bfr[cur][nb][hi], bfr[cur][nb][2 + hi]);
                }
        }
    }

    // ---------------- epilogue: merge k-slices via smem ----------------
    __syncthreads();   // all warps done reading stage buffers

    if (kg == 1) {
        float* dst = (float*)(smem_raw + (wm * 2 + wn) * 16384);
#pragma unroll
        for (int mt = 0; mt < 4; mt++)
#pragma unroll
            for (int nt = 0; nt < 8; nt++) {
                float4 v = make_float4(acc[mt][nt][0], acc[mt][nt][1], acc[mt][nt][2], acc[mt][nt][3]);
                *(float4*)&dst[((mt * 8 + nt) * 32 + lane) * 4] = v;
            }
    }
    __syncthreads();

    if (kg == 0) {
        const float* prt = (const float*)(smem_raw + (wm * 2 + wn) * 16384);
        const int gid = lane >> 2;
        const int tg  = lane & 3;
#pragma unroll
        for (int mt = 0; mt < 4; mt++) {
#pragma unroll
            for (int nt = 0; nt < 8; nt++) {
                float4 p = *(const float4*)&prt[((mt * 8 + nt) * 32 + lane) * 4];
                int row = m0 + wm * 64 + mt * 16 + gid;
                int col = n0 + wn * 64 + nt * 8 + tg * 2;
                float2 bb = *(const float2*)&g_bias[col];
                float2 v0 = make_float2(acc[mt][nt][0] + p.x + bb.x, acc[mt][nt][1] + p.y + bb.y);
                float2 v1 = make_float2(acc[mt][nt][2] + p.z + bb.x, acc[mt][nt][3] + p.w + bb.y);
                *(float2*)&out[(size_t)row * NTOT + col]       = v0;
                *(float2*)&out[(size_t)(row + 8) * NTOT + col] = v1;
            }
        }
    }
}

// ---------------- launch ----------------
extern "C" void kernel_launch(void* const* d_in, const int* in_sizes, int n_in,
                              void* d_out, int out_size) {
    const float* xre  = (const float*)d_in[0];
    const float* xim  = (const float*)d_in[1];
    const float* rw   = (const float*)d_in[2];
    const float* cw   = (const float*)d_in[3];
    const float* swre = (const float*)d_in[4];
    const float* swim = (const float*)d_in[5];
    const float* bre  = (const float*)d_in[6];
    const float* bim  = (const float*)d_in[7];
    float* out = (float*)d_out;

    static bool attr_set = false;
    if (!attr_set) {
        cudaFuncSetAttribute(gemm_kernel, cudaFuncAttributeMaxDynamicSharedMemorySize, SMEM_BYTES);
        attr_set = true;
    }

    prep_all<<<XBLOCKS + WT_BLOCKS + WS_BLOCKS + NTOT, 256>>>(
        xre, xim, rw, cw, swre, swim, bre, bim);
    gemm_kernel<<<dim3(NTOT / NTILE, BDIM / MTILE), 256, SMEM_BYTES>>>(out);
}